// round 1
// baseline (speedup 1.0000x reference)
#include <cuda_runtime.h>
#include <vector>
#include <algorithm>

// ---------------- problem constants ----------------
#define B_    8
#define S_    4096
#define D_    512
#define QT    32          // queries per block
#define NTH   256         // threads per block
#define SCP   132         // padded score row (>=129)
#define NDEP  8

// ---------------- host-side Cantor tables ----------------
// Exact float64 replication of the reference's recursion + *(S-1) + int trunc + unique.
struct CTab { int idx[SCP]; int dmin[SCP]; };
static CTab g_tab;
static int  g_nu = 0;

static bool build_tables() {
    std::vector<std::vector<long long>> idxd;
    auto to_idx = [](const std::vector<double>& p) {
        std::vector<long long> v;
        v.reserve(p.size());
        for (double x : p) v.push_back((long long)(x * 4095.0));  // trunc toward zero, x>=0
        std::sort(v.begin(), v.end());
        v.erase(std::unique(v.begin(), v.end()), v.end());
        return v;
    };
    std::vector<double> prev = {0.0, 1.0};
    idxd.push_back(to_idx(prev));
    for (int d = 1; d < NDEP; ++d) {
        std::vector<double> nw;
        nw.reserve(prev.size() * 2);
        for (size_t i = 0; i + 1 < prev.size(); ++i) {
            double left  = prev[i];
            double right = prev[i + 1];
            double third = (right - left) / 3.0;
            nw.push_back(left);
            nw.push_back(left + third);
        }
        nw.push_back(prev.back());
        prev.swap(nw);
        idxd.push_back(to_idx(prev));
    }
    const std::vector<long long>& uni = idxd[NDEP - 1];  // nested -> union == deepest
    g_nu = (int)uni.size();
    if (g_nu > SCP) g_nu = SCP;  // cannot happen (max 129), safety only
    for (int j = 0; j < g_nu; ++j) {
        g_tab.idx[j] = (int)uni[j];
        g_tab.dmin[j] = NDEP - 1;
        for (int d = 0; d < NDEP; ++d) {
            if (std::binary_search(idxd[d].begin(), idxd[d].end(), uni[j])) {
                g_tab.dmin[j] = d;
                break;
            }
        }
    }
    return true;
}
static bool g_built = build_tables();

// ---------------- kernel ----------------
__global__ __launch_bounds__(NTH, 2)
void ufa_kernel(const float* __restrict__ Q, const float* __restrict__ K,
                const float* __restrict__ V, const float* __restrict__ SW,
                const float* __restrict__ ST, float* __restrict__ O,
                CTab tab, int nu)
{
    extern __shared__ float smem[];
    float* qs = smem;                 // QT*D floats (reused as V tile in phase 4)
    float* sc = smem + QT * D_;       // QT*SCP score/coeff rows
    __shared__ float wv[NDEP];
    __shared__ int   si[SCP];
    __shared__ int   sd[SCP];

    const int tid = threadIdx.x;
    const int w   = tid >> 5;
    const int l   = tid & 31;
    const int b   = blockIdx.y;
    const int q0  = blockIdx.x * QT;

    // tables -> shared; depth weight softmax (done redundantly per block, trivial)
    for (int i = tid; i < nu; i += NTH) { si[i] = tab.idx[i]; sd[i] = tab.dmin[i]; }
    if (tid == 0) {
        float tmp = ST[0];
        float vv[NDEP];
        float m = -1e30f;
        #pragma unroll
        for (int d = 0; d < NDEP; ++d) { vv[d] = SW[d] / tmp; m = fmaxf(m, vv[d]); }
        float s = 0.f;
        #pragma unroll
        for (int d = 0; d < NDEP; ++d) { vv[d] = expf(vv[d] - m); s += vv[d]; }
        #pragma unroll
        for (int d = 0; d < NDEP; ++d) wv[d] = vv[d] / s;
    }

    // ---- phase 1: Q tile -> smem ----
    const float4* Qg  = (const float4*)(Q + ((size_t)b * S_ + q0) * D_);
    float4*       qs4 = (float4*)qs;
    #pragma unroll 4
    for (int i = tid; i < QT * (D_ / 4); i += NTH) qs4[i] = Qg[i];
    __syncthreads();

    const float inv_scale = 1.0f / sqrtf((float)D_);

    // ---- phase 2: scores  sc[q][j] = (Q[q] . K[idx_j]) * inv_scale ----
    for (int j = w; j < nu; j += 8) {
        const float4* k4 = (const float4*)(K + ((size_t)b * S_ + si[j]) * D_);
        float4 kv0 = k4[l];
        float4 kv1 = k4[32 + l];
        float4 kv2 = k4[64 + l];
        float4 kv3 = k4[96 + l];
        #pragma unroll 4
        for (int q = 0; q < QT; ++q) {
            const float4* q4 = qs4 + q * (D_ / 4);
            float4 a0 = q4[l];
            float4 a1 = q4[32 + l];
            float4 a2 = q4[64 + l];
            float4 a3 = q4[96 + l];
            float acc0 = a0.x * kv0.x;
            float acc1 = a1.x * kv1.x;
            acc0 = fmaf(a0.y, kv0.y, acc0); acc1 = fmaf(a1.y, kv1.y, acc1);
            acc0 = fmaf(a0.z, kv0.z, acc0); acc1 = fmaf(a1.z, kv1.z, acc1);
            acc0 = fmaf(a0.w, kv0.w, acc0); acc1 = fmaf(a1.w, kv1.w, acc1);
            acc0 = fmaf(a2.x, kv2.x, acc0); acc1 = fmaf(a3.x, kv3.x, acc1);
            acc0 = fmaf(a2.y, kv2.y, acc0); acc1 = fmaf(a3.y, kv3.y, acc1);
            acc0 = fmaf(a2.z, kv2.z, acc0); acc1 = fmaf(a3.z, kv3.z, acc1);
            acc0 = fmaf(a2.w, kv2.w, acc0); acc1 = fmaf(a3.w, kv3.w, acc1);
            float acc = acc0 + acc1;
            #pragma unroll
            for (int off = 16; off; off >>= 1)
                acc += __shfl_xor_sync(0xffffffffu, acc, off);
            if (l == 0) sc[q * SCP + j] = acc * inv_scale;
        }
    }
    __syncthreads();

    // ---- phase 3: fuse 8 nested softmaxes into one coefficient per key ----
    // e_j = exp(s_j - m);  Z_d = sum_{dmin<=d} e;  c_j = e_j * sum_{d>=dmin_j} w_d/Z_d
    for (int q = w; q < QT; q += 8) {
        float* row = sc + q * SCP;
        float m = -1e30f;
        for (int j = l; j < nu; j += 32) m = fmaxf(m, row[j]);
        #pragma unroll
        for (int off = 16; off; off >>= 1)
            m = fmaxf(m, __shfl_xor_sync(0xffffffffu, m, off));
        float g[NDEP];
        #pragma unroll
        for (int d = 0; d < NDEP; ++d) g[d] = 0.f;
        for (int j = l; j < nu; j += 32) {
            float e = expf(row[j] - m);
            row[j] = e;
            g[sd[j]] += e;
        }
        #pragma unroll
        for (int d = 0; d < NDEP; ++d)
            #pragma unroll
            for (int off = 16; off; off >>= 1)
                g[d] += __shfl_xor_sync(0xffffffffu, g[d], off);
        float Z = 0.f, sa[NDEP];
        #pragma unroll
        for (int d = 0; d < NDEP; ++d) { Z += g[d]; sa[d] = wv[d] / Z; }
        float s = 0.f;
        #pragma unroll
        for (int d = NDEP - 1; d >= 0; --d) { s += sa[d]; sa[d] = s; }
        for (int j = l; j < nu; j += 32) row[j] *= sa[sd[j]];
    }
    __syncthreads();

    // ---- phase 4: out[q] = sum_j c[q][j] * V[idx_j]  (V tiles staged via smem) ----
    float4* vs4 = (float4*)qs;  // 16 rows * 128 float4 = 32 KB, fits the Q region
    float4 acc[4][4];
    #pragma unroll
    for (int a = 0; a < 4; ++a)
        #pragma unroll
        for (int c = 0; c < 4; ++c)
            acc[a][c] = make_float4(0.f, 0.f, 0.f, 0.f);

    for (int j0 = 0; j0 < nu; j0 += 16) {
        int jn = min(16, nu - j0);
        __syncthreads();  // previous tile fully consumed before overwrite
        for (int i = tid; i < jn * 128; i += NTH) {
            int r = i >> 7, c = i & 127;
            vs4[i] = ((const float4*)(V + ((size_t)b * S_ + si[j0 + r]) * D_))[c];
        }
        __syncthreads();
        for (int jj = 0; jj < jn; ++jj) {
            float4 vv0 = vs4[jj * 128 + l];
            float4 vv1 = vs4[jj * 128 + 32 + l];
            float4 vv2 = vs4[jj * 128 + 64 + l];
            float4 vv3 = vs4[jj * 128 + 96 + l];
            #pragma unroll
            for (int qq = 0; qq < 4; ++qq) {
                float cf = sc[(w * 4 + qq) * SCP + j0 + jj];
                acc[qq][0].x = fmaf(cf, vv0.x, acc[qq][0].x);
                acc[qq][0].y = fmaf(cf, vv0.y, acc[qq][0].y);
                acc[qq][0].z = fmaf(cf, vv0.z, acc[qq][0].z);
                acc[qq][0].w = fmaf(cf, vv0.w, acc[qq][0].w);
                acc[qq][1].x = fmaf(cf, vv1.x, acc[qq][1].x);
                acc[qq][1].y = fmaf(cf, vv1.y, acc[qq][1].y);
                acc[qq][1].z = fmaf(cf, vv1.z, acc[qq][1].z);
                acc[qq][1].w = fmaf(cf, vv1.w, acc[qq][1].w);
                acc[qq][2].x = fmaf(cf, vv2.x, acc[qq][2].x);
                acc[qq][2].y = fmaf(cf, vv2.y, acc[qq][2].y);
                acc[qq][2].z = fmaf(cf, vv2.z, acc[qq][2].z);
                acc[qq][2].w = fmaf(cf, vv2.w, acc[qq][2].w);
                acc[qq][3].x = fmaf(cf, vv3.x, acc[qq][3].x);
                acc[qq][3].y = fmaf(cf, vv3.y, acc[qq][3].y);
                acc[qq][3].z = fmaf(cf, vv3.z, acc[qq][3].z);
                acc[qq][3].w = fmaf(cf, vv3.w, acc[qq][3].w);
            }
        }
    }

    // ---- store ----
    #pragma unroll
    for (int qq = 0; qq < 4; ++qq) {
        int q = w * 4 + qq;
        float4* og = (float4*)(O + ((size_t)b * S_ + q0 + q) * D_);
        og[l]      = acc[qq][0];
        og[32 + l] = acc[qq][1];
        og[64 + l] = acc[qq][2];
        og[96 + l] = acc[qq][3];
    }
}

// ---------------- launch ----------------
extern "C" void kernel_launch(void* const* d_in, const int* in_sizes, int n_in,
                              void* d_out, int out_size)
{
    const float* Q  = (const float*)d_in[0];
    const float* K  = (const float*)d_in[1];
    const float* V  = (const float*)d_in[2];
    // d_in[3] = t (unused by the reference)
    const float* SW = (const float*)d_in[4];
    const float* ST = (const float*)d_in[5];
    float* O = (float*)d_out;

    const int smem_bytes = (QT * D_ + QT * SCP) * (int)sizeof(float);  // 82432
    cudaFuncSetAttribute(ufa_kernel, cudaFuncAttributeMaxDynamicSharedMemorySize, smem_bytes);

    dim3 grid(S_ / QT, B_);
    ufa_kernel<<<grid, NTH, smem_bytes>>>(Q, K, V, SW, ST, O, g_tab, g_nu);
}

// round 3
// speedup vs baseline: 2.2670x; 2.2670x over previous
#include <cuda_runtime.h>
#include <vector>
#include <algorithm>
#include <cstring>

// ---------------- problem constants ----------------
#define B_    8
#define S_    4096
#define D_    512
#define QT    128        // queries per block
#define NTH   256        // threads per block
#define NDEP  8
#define NJP   132        // padded union key count (real nu = 129)
#define RP    132        // padded row length (floats) for smem tiles
#define KC    32         // k-chunk for score GEMM

// ---------------- host-side Cantor tables ----------------
// Exact float64 replication of the reference recursion + *(S-1) + trunc + unique.
// Keys are reordered by (dmin, idx) so depth-group boundaries are static.
struct CTab { int idx[NJP]; int bnd[NDEP + 1]; int nu; };
static CTab g_tab;

static bool build_tables() {
    std::vector<std::vector<long long>> idxd;
    auto to_idx = [](const std::vector<double>& p) {
        std::vector<long long> v;
        v.reserve(p.size());
        for (double x : p) v.push_back((long long)(x * 4095.0));
        std::sort(v.begin(), v.end());
        v.erase(std::unique(v.begin(), v.end()), v.end());
        return v;
    };
    std::vector<double> prev = {0.0, 1.0};
    idxd.push_back(to_idx(prev));
    for (int d = 1; d < NDEP; ++d) {
        std::vector<double> nw;
        nw.reserve(prev.size() * 2);
        for (size_t i = 0; i + 1 < prev.size(); ++i) {
            double left  = prev[i];
            double right = prev[i + 1];
            double third = (right - left) / 3.0;
            nw.push_back(left);
            nw.push_back(left + third);
        }
        nw.push_back(prev.back());
        prev.swap(nw);
        idxd.push_back(to_idx(prev));
    }
    const std::vector<long long>& uni = idxd[NDEP - 1];   // nested -> union == deepest
    int nu = (int)uni.size();
    if (nu > NJP) nu = NJP;
    // (dmin, idx) pairs
    std::vector<std::pair<int, long long>> keys;
    for (int j = 0; j < nu; ++j) {
        int dm = NDEP - 1;
        for (int d = 0; d < NDEP; ++d)
            if (std::binary_search(idxd[d].begin(), idxd[d].end(), uni[j])) { dm = d; break; }
        keys.push_back({dm, uni[j]});
    }
    std::sort(keys.begin(), keys.end());
    for (int j = 0; j < nu; ++j) g_tab.idx[j] = (int)keys[j].second;
    for (int j = nu; j < NJP; ++j) g_tab.idx[j] = g_tab.idx[0];  // pad rows (coeff forced 0)
    for (int d = 0; d <= NDEP; ++d) {
        int c = 0;
        for (auto& kv : keys) if (kv.first < d) ++c;
        g_tab.bnd[d] = c;
    }
    g_tab.nu = nu;
    return true;
}
static bool g_built = build_tables();

// ---------------- packed f32x2 helpers ----------------
typedef unsigned long long ull;

__device__ __forceinline__ ull dup2(float x) {
    ull r;
    asm("mov.b64 %0, {%1, %1};" : "=l"(r) : "r"(__float_as_uint(x)));
    return r;
}
__device__ __forceinline__ void fma2(ull& d, ull a, ull b) {
    asm("fma.rn.f32x2 %0, %1, %2, %0;" : "+l"(d) : "l"(a), "l"(b));
}
__device__ __forceinline__ float2 u2f(ull v) {
    float2 f;
    memcpy(&f, &v, 8);
    return f;
}

// ---------------- kernel ----------------
__global__ __launch_bounds__(NTH, 2)
void ufa2_kernel(const float* __restrict__ Q, const float* __restrict__ K,
                 const float* __restrict__ V, const float* __restrict__ SW,
                 const float* __restrict__ ST, float* __restrict__ O, CTab tab)
{
    extern __shared__ float sm[];
    float* cs = sm;                    // NJP x RP  coefficient/score matrix [j][q]
    float* Qs = sm + NJP * RP;         // KC x RP   (k-major Q chunk)
    float* Ks = Qs + KC * RP;          // KC x RP   (k-major K chunk)
    float* Vs = Qs;                    // 32 x RP   V tile (reuses Qs/Ks region in phase 4)

    __shared__ int   si[NJP];
    __shared__ float wv[NDEP];

    const int tid   = threadIdx.x;
    const int b     = blockIdx.y;
    const int q0blk = blockIdx.x * QT;
    const int nu    = tab.nu;
    const float inv_scale = 0.04419417382415922f;  // 1/sqrt(512)

    const int qg  = tid >> 4;          // 0..15  (8 queries each)
    const int jg  = tid & 15;          // 0..15  (8 keys / 8 dims each)
    const int qq0 = qg * 8;
    const int jj0 = jg * 8;

    for (int i = tid; i < NJP; i += NTH) si[i] = tab.idx[i];
    if (tid == 0) {
        float tmp = ST[0];
        float vvv[NDEP];
        float m = -1e30f;
        #pragma unroll
        for (int d = 0; d < NDEP; ++d) { vvv[d] = SW[d] / tmp; m = fmaxf(m, vvv[d]); }
        float s = 0.f;
        #pragma unroll
        for (int d = 0; d < NDEP; ++d) { vvv[d] = __expf(vvv[d] - m); s += vvv[d]; }
        #pragma unroll
        for (int d = 0; d < NDEP; ++d) wv[d] = vvv[d] / s;
    }
    __syncthreads();

    // ---- extra score columns (j >= 128): tiny dedicated pass ----
    for (int jx = 128; jx < nu; ++jx) {
        int q = tid >> 1, h = tid & 1;
        const float4* qr = (const float4*)(Q + ((size_t)b * S_ + q0blk + q) * D_ + h * 256);
        const float4* kr = (const float4*)(K + ((size_t)b * S_ + si[jx]) * D_ + h * 256);
        float s = 0.f;
        #pragma unroll 8
        for (int i = 0; i < 64; ++i) {
            float4 a = qr[i];
            float4 c = kr[i];
            s = fmaf(a.x, c.x, s);
            s = fmaf(a.y, c.y, s);
            s = fmaf(a.z, c.z, s);
            s = fmaf(a.w, c.w, s);
        }
        s += __shfl_xor_sync(0xffffffffu, s, 1);
        if (h == 0) cs[jx * RP + q] = s * inv_scale;
    }

    // ---- phase A: score GEMM  S[128q x 128j] = Q . K^T ----
    ull acc[4][8];
    #pragma unroll
    for (int p = 0; p < 4; ++p)
        #pragma unroll
        for (int i = 0; i < 8; ++i)
            acc[p][i] = 0ull;

    #pragma unroll 1
    for (int ck = 0; ck < D_ / KC; ++ck) {
        __syncthreads();
        // fill Qs / Ks (k-major, transposed store)
        {
            int qr = tid >> 3, kq = tid & 7;
            #pragma unroll
            for (int r = 0; r < 4; ++r) {
                int q = qr + 32 * r;
                float4 v = *(const float4*)(Q + ((size_t)b * S_ + q0blk + q) * D_ + ck * KC + kq * 4);
                Qs[(kq * 4 + 0) * RP + q] = v.x;
                Qs[(kq * 4 + 1) * RP + q] = v.y;
                Qs[(kq * 4 + 2) * RP + q] = v.z;
                Qs[(kq * 4 + 3) * RP + q] = v.w;
                float4 u = *(const float4*)(K + ((size_t)b * S_ + si[q]) * D_ + ck * KC + kq * 4);
                Ks[(kq * 4 + 0) * RP + q] = u.x;
                Ks[(kq * 4 + 1) * RP + q] = u.y;
                Ks[(kq * 4 + 2) * RP + q] = u.z;
                Ks[(kq * 4 + 3) * RP + q] = u.w;
            }
        }
        __syncthreads();
        #pragma unroll 4
        for (int k = 0; k < KC; ++k) {
            const float* kr = Ks + k * RP + jj0;
            float4 ka = *(const float4*)kr;
            float4 kb = *(const float4*)(kr + 4);
            ull kd0 = dup2(ka.x), kd1 = dup2(ka.y), kd2 = dup2(ka.z), kd3 = dup2(ka.w);
            ull kd4 = dup2(kb.x), kd5 = dup2(kb.y), kd6 = dup2(kb.z), kd7 = dup2(kb.w);
            const float* qrp = Qs + k * RP + qq0;
            ull qp0 = *(const ull*)(qrp + 0);
            ull qp1 = *(const ull*)(qrp + 2);
            ull qp2 = *(const ull*)(qrp + 4);
            ull qp3 = *(const ull*)(qrp + 6);
            fma2(acc[0][0], qp0, kd0); fma2(acc[0][1], qp0, kd1);
            fma2(acc[0][2], qp0, kd2); fma2(acc[0][3], qp0, kd3);
            fma2(acc[0][4], qp0, kd4); fma2(acc[0][5], qp0, kd5);
            fma2(acc[0][6], qp0, kd6); fma2(acc[0][7], qp0, kd7);
            fma2(acc[1][0], qp1, kd0); fma2(acc[1][1], qp1, kd1);
            fma2(acc[1][2], qp1, kd2); fma2(acc[1][3], qp1, kd3);
            fma2(acc[1][4], qp1, kd4); fma2(acc[1][5], qp1, kd5);
            fma2(acc[1][6], qp1, kd6); fma2(acc[1][7], qp1, kd7);
            fma2(acc[2][0], qp2, kd0); fma2(acc[2][1], qp2, kd1);
            fma2(acc[2][2], qp2, kd2); fma2(acc[2][3], qp2, kd3);
            fma2(acc[2][4], qp2, kd4); fma2(acc[2][5], qp2, kd5);
            fma2(acc[2][6], qp2, kd6); fma2(acc[2][7], qp2, kd7);
            fma2(acc[3][0], qp3, kd0); fma2(acc[3][1], qp3, kd1);
            fma2(acc[3][2], qp3, kd2); fma2(acc[3][3], qp3, kd3);
            fma2(acc[3][4], qp3, kd4); fma2(acc[3][5], qp3, kd5);
            fma2(acc[3][6], qp3, kd6); fma2(acc[3][7], qp3, kd7);
        }
    }

    // scaled transposed writeback: cs[j][q]
    #pragma unroll
    for (int p = 0; p < 4; ++p)
        #pragma unroll
        for (int i = 0; i < 8; ++i) {
            float2 e = u2f(acc[p][i]);
            float2 o = make_float2(e.x * inv_scale, e.y * inv_scale);
            *(float2*)(cs + (jj0 + i) * RP + qq0 + 2 * p) = o;
        }
    __syncthreads();

    // ---- phase 3: fused nested softmax -> per-key coefficient ----
    if (tid < QT) {
        const int q = tid;
        float m = -1e30f;
        for (int j = 0; j < nu; ++j) m = fmaxf(m, cs[j * RP + q]);
        float gs[NDEP];
        #pragma unroll
        for (int d = 0; d < NDEP; ++d) {
            float s = 0.f;
            for (int j = tab.bnd[d]; j < tab.bnd[d + 1]; ++j) {
                float e = __expf(cs[j * RP + q] - m);
                cs[j * RP + q] = e;
                s += e;
            }
            gs[d] = s;
        }
        float Z = 0.f, sa[NDEP];
        #pragma unroll
        for (int d = 0; d < NDEP; ++d) { Z += gs[d]; sa[d] = __fdividef(wv[d], Z); }
        float ss = 0.f;
        #pragma unroll
        for (int d = NDEP - 1; d >= 0; --d) { ss += sa[d]; sa[d] = ss; }
        #pragma unroll
        for (int d = 0; d < NDEP; ++d)
            for (int j = tab.bnd[d]; j < tab.bnd[d + 1]; ++j)
                cs[j * RP + q] *= sa[d];
        for (int j = nu; j < NJP; ++j) cs[j * RP + q] = 0.f;
    }

    // ---- phase 4: out[128q x 512d] = C . V, d in 4 chunks of 128 ----
    const int dd0 = jg * 8;
    #pragma unroll 1
    for (int dc = 0; dc < 4; ++dc) {
        ull av[4][8];
        #pragma unroll
        for (int p = 0; p < 4; ++p)
            #pragma unroll
            for (int i = 0; i < 8; ++i)
                av[p][i] = 0ull;

        #pragma unroll 1
        for (int jt = 0; jt < NJP; jt += 32) {
            const int jn = min(32, NJP - jt);   // last tile has 4 rows (129..131 padded)
            __syncthreads();
            {
                int w = tid >> 5, lane = tid & 31;
                #pragma unroll
                for (int rr = 0; rr < 4; ++rr) {
                    int jr = w + 8 * rr;
                    if (jr < jn) {
                        float4 v = *(const float4*)(V + ((size_t)b * S_ + si[jt + jr]) * D_ + dc * 128 + lane * 4);
                        *(float4*)(Vs + jr * RP + lane * 4) = v;
                    }
                }
            }
            __syncthreads();
            #pragma unroll 4
            for (int jj = 0; jj < jn; ++jj) {
                const float* vr = Vs + jj * RP + dd0;
                float4 va = *(const float4*)vr;
                float4 vb = *(const float4*)(vr + 4);
                ull vd0 = dup2(va.x), vd1 = dup2(va.y), vd2 = dup2(va.z), vd3 = dup2(va.w);
                ull vd4 = dup2(vb.x), vd5 = dup2(vb.y), vd6 = dup2(vb.z), vd7 = dup2(vb.w);
                const float* crp = cs + (jt + jj) * RP + qq0;
                ull cp0 = *(const ull*)(crp + 0);
                ull cp1 = *(const ull*)(crp + 2);
                ull cp2 = *(const ull*)(crp + 4);
                ull cp3 = *(const ull*)(crp + 6);
                fma2(av[0][0], cp0, vd0); fma2(av[0][1], cp0, vd1);
                fma2(av[0][2], cp0, vd2); fma2(av[0][3], cp0, vd3);
                fma2(av[0][4], cp0, vd4); fma2(av[0][5], cp0, vd5);
                fma2(av[0][6], cp0, vd6); fma2(av[0][7], cp0, vd7);
                fma2(av[1][0], cp1, vd0); fma2(av[1][1], cp1, vd1);
                fma2(av[1][2], cp1, vd2); fma2(av[1][3], cp1, vd3);
                fma2(av[1][4], cp1, vd4); fma2(av[1][5], cp1, vd5);
                fma2(av[1][6], cp1, vd6); fma2(av[1][7], cp1, vd7);
                fma2(av[2][0], cp2, vd0); fma2(av[2][1], cp2, vd1);
                fma2(av[2][2], cp2, vd2); fma2(av[2][3], cp2, vd3);
                fma2(av[2][4], cp2, vd4); fma2(av[2][5], cp2, vd5);
                fma2(av[2][6], cp2, vd6); fma2(av[2][7], cp2, vd7);
                fma2(av[3][0], cp3, vd0); fma2(av[3][1], cp3, vd1);
                fma2(av[3][2], cp3, vd2); fma2(av[3][3], cp3, vd3);
                fma2(av[3][4], cp3, vd4); fma2(av[3][5], cp3, vd5);
                fma2(av[3][6], cp3, vd6); fma2(av[3][7], cp3, vd7);
            }
        }

        // write O chunk
        #pragma unroll
        for (int p = 0; p < 4; ++p) {
            float2 e0 = u2f(av[p][0]), e1 = u2f(av[p][1]), e2 = u2f(av[p][2]), e3 = u2f(av[p][3]);
            float2 e4 = u2f(av[p][4]), e5 = u2f(av[p][5]), e6 = u2f(av[p][6]), e7 = u2f(av[p][7]);
            size_t base = ((size_t)b * S_ + q0blk + qq0 + 2 * p) * D_ + dc * 128 + dd0;
            *(float4*)(O + base + 0) = make_float4(e0.x, e1.x, e2.x, e3.x);
            *(float4*)(O + base + 4) = make_float4(e4.x, e5.x, e6.x, e7.x);
            *(float4*)(O + base + D_ + 0) = make_float4(e0.y, e1.y, e2.y, e3.y);
            *(float4*)(O + base + D_ + 4) = make_float4(e4.y, e5.y, e6.y, e7.y);
        }
    }
}

// ---------------- launch ----------------
extern "C" void kernel_launch(void* const* d_in, const int* in_sizes, int n_in,
                              void* d_out, int out_size)
{
    const float* Q  = (const float*)d_in[0];
    const float* K  = (const float*)d_in[1];
    const float* V  = (const float*)d_in[2];
    // d_in[3] = t (unused by the reference)
    const float* SW = (const float*)d_in[4];
    const float* ST = (const float*)d_in[5];
    float* O = (float*)d_out;

    const int smem_bytes = (NJP * RP + 2 * KC * RP) * (int)sizeof(float);  // ~103.5 KB
    cudaFuncSetAttribute(ufa2_kernel, cudaFuncAttributeMaxDynamicSharedMemorySize, smem_bytes);

    dim3 grid(S_ / QT, B_);
    ufa2_kernel<<<grid, NTH, smem_bytes>>>(Q, K, V, SW, ST, O, g_tab);
}

// round 4
// speedup vs baseline: 2.3547x; 1.0387x over previous
#include <cuda_runtime.h>
#include <vector>
#include <algorithm>
#include <cstring>

// ---------------- problem constants ----------------
#define B_    8
#define S_    4096
#define D_    512
#define QT    128        // queries per block
#define NTH   256        // threads per block
#define NDEP  8
#define NJP   132        // padded union key count (real nu = 129)
#define RP    132        // padded row length (floats) for smem tiles
#define KC    32         // k-chunk for score GEMM

// smem float offsets
#define DBUF_STRIDE (2 * KC * RP)        // 8448 floats per (Q,K) buffer pair
#define VS_OFF      (NJP * RP)           // 17424
#define VS_STRIDE   (32 * RP)            // 4224
#define SMEM_FLOATS (VS_OFF + 2 * VS_STRIDE)  // 25872 -> 103488 B

// ---------------- host-side Cantor tables ----------------
struct CTab { int idx[NJP]; int bnd[NDEP + 1]; int nu; };
static CTab g_tab;

static bool build_tables() {
    std::vector<std::vector<long long>> idxd;
    auto to_idx = [](const std::vector<double>& p) {
        std::vector<long long> v;
        v.reserve(p.size());
        for (double x : p) v.push_back((long long)(x * 4095.0));
        std::sort(v.begin(), v.end());
        v.erase(std::unique(v.begin(), v.end()), v.end());
        return v;
    };
    std::vector<double> prev = {0.0, 1.0};
    idxd.push_back(to_idx(prev));
    for (int d = 1; d < NDEP; ++d) {
        std::vector<double> nw;
        nw.reserve(prev.size() * 2);
        for (size_t i = 0; i + 1 < prev.size(); ++i) {
            double left  = prev[i];
            double right = prev[i + 1];
            double third = (right - left) / 3.0;
            nw.push_back(left);
            nw.push_back(left + third);
        }
        nw.push_back(prev.back());
        prev.swap(nw);
        idxd.push_back(to_idx(prev));
    }
    const std::vector<long long>& uni = idxd[NDEP - 1];
    int nu = (int)uni.size();
    if (nu > NJP) nu = NJP;
    std::vector<std::pair<int, long long>> keys;
    for (int j = 0; j < nu; ++j) {
        int dm = NDEP - 1;
        for (int d = 0; d < NDEP; ++d)
            if (std::binary_search(idxd[d].begin(), idxd[d].end(), uni[j])) { dm = d; break; }
        keys.push_back({dm, uni[j]});
    }
    std::sort(keys.begin(), keys.end());
    for (int j = 0; j < nu; ++j) g_tab.idx[j] = (int)keys[j].second;
    for (int j = nu; j < NJP; ++j) g_tab.idx[j] = g_tab.idx[0];
    for (int d = 0; d <= NDEP; ++d) {
        int c = 0;
        for (auto& kv : keys) if (kv.first < d) ++c;
        g_tab.bnd[d] = c;
    }
    g_tab.nu = nu;
    return true;
}
static bool g_built = build_tables();

// ---------------- packed f32x2 helpers ----------------
typedef unsigned long long ull;

__device__ __forceinline__ ull dup2(float x) {
    ull r;
    asm("mov.b64 %0, {%1, %1};" : "=l"(r) : "r"(__float_as_uint(x)));
    return r;
}
__device__ __forceinline__ void fma2(ull& d, ull a, ull b) {
    asm("fma.rn.f32x2 %0, %1, %2, %0;" : "+l"(d) : "l"(a), "l"(b));
}
__device__ __forceinline__ float2 u2f(ull v) {
    float2 f;
    memcpy(&f, &v, 8);
    return f;
}

// ---------------- kernel ----------------
__global__ __launch_bounds__(NTH, 2)
void ufa3_kernel(const float* __restrict__ Q, const float* __restrict__ K,
                 const float* __restrict__ V, const float* __restrict__ SW,
                 const float* __restrict__ ST, float* __restrict__ O, CTab tab)
{
    extern __shared__ float sm[];
    float* cs = sm;                    // NJP x RP  [j][q]; rows 0..127 double as phase-A dbuf

    __shared__ int   si[NJP];
    __shared__ float wv[NDEP];

    const int tid   = threadIdx.x;
    const int b     = blockIdx.y;
    const int q0blk = blockIdx.x * QT;
    const int nu    = tab.nu;
    const float inv_scale = 0.04419417382415922f;  // 1/sqrt(512)

    const int qg  = tid >> 4;          // 0..15
    const int jg  = tid & 15;          // 0..15
    const int qq0 = qg * 8;
    const int jj0 = jg * 8;

    for (int i = tid; i < NJP; i += NTH) si[i] = tab.idx[i];
    if (tid == 0) {
        float tmp = ST[0];
        float vvv[NDEP];
        float m = -1e30f;
        #pragma unroll
        for (int d = 0; d < NDEP; ++d) { vvv[d] = SW[d] / tmp; m = fmaxf(m, vvv[d]); }
        float s = 0.f;
        #pragma unroll
        for (int d = 0; d < NDEP; ++d) { vvv[d] = __expf(vvv[d] - m); s += vvv[d]; }
        #pragma unroll
        for (int d = 0; d < NDEP; ++d) wv[d] = vvv[d] / s;
    }
    __syncthreads();

    // ---- score column j = 128 (only key beyond the 128x128 GEMM); writes cs row 128
    //      (outside the phase-A double-buffer region: dbuf = rows 0..127) ----
    {
        int q = tid >> 1, h = tid & 1;
        const float4* qr4 = (const float4*)(Q + ((size_t)b * S_ + q0blk + q) * D_ + h * 256);
        const float4* kr4 = (const float4*)(K + ((size_t)b * S_ + si[128]) * D_ + h * 256);
        float s = 0.f;
        #pragma unroll 8
        for (int i = 0; i < 64; ++i) {
            float4 a = qr4[i];
            float4 c = kr4[i];
            s = fmaf(a.x, c.x, s);
            s = fmaf(a.y, c.y, s);
            s = fmaf(a.z, c.z, s);
            s = fmaf(a.w, c.w, s);
        }
        s += __shfl_xor_sync(0xffffffffu, s, 1);
        if (h == 0) cs[128 * RP + q] = s * inv_scale;
    }

    // ---- phase A: score GEMM  S[128q x 128j] = Q . K^T  (double-buffered) ----
    const int fqr = tid >> 3;          // 0..31
    const int fkq = tid & 7;           // 0..7

    ull acc[4][8];
    #pragma unroll
    for (int p = 0; p < 4; ++p)
        #pragma unroll
        for (int i = 0; i < 8; ++i)
            acc[p][i] = 0ull;

    // fill chunk ck into buffer s
    auto fillA = [&](int ck, int s) {
        float* Qb = sm + s * DBUF_STRIDE;
        float* Kb = Qb + KC * RP;
        #pragma unroll
        for (int r = 0; r < 4; ++r) {
            int q = fqr + 32 * r;
            float4 v = *(const float4*)(Q + ((size_t)b * S_ + q0blk + q) * D_ + ck * KC + fkq * 4);
            Qb[(fkq * 4 + 0) * RP + q] = v.x;
            Qb[(fkq * 4 + 1) * RP + q] = v.y;
            Qb[(fkq * 4 + 2) * RP + q] = v.z;
            Qb[(fkq * 4 + 3) * RP + q] = v.w;
            float4 u = *(const float4*)(K + ((size_t)b * S_ + si[q]) * D_ + ck * KC + fkq * 4);
            Kb[(fkq * 4 + 0) * RP + q] = u.x;
            Kb[(fkq * 4 + 1) * RP + q] = u.y;
            Kb[(fkq * 4 + 2) * RP + q] = u.z;
            Kb[(fkq * 4 + 3) * RP + q] = u.w;
        }
    };

    fillA(0, 0);
    __syncthreads();

    #pragma unroll 1
    for (int ck = 0; ck < D_ / KC; ++ck) {
        const int s = ck & 1;
        if (ck < D_ / KC - 1) fillA(ck + 1, s ^ 1);

        const float* Qb = sm + s * DBUF_STRIDE;
        const float* Kb = Qb + KC * RP;
        #pragma unroll 4
        for (int k = 0; k < KC; ++k) {
            const float* kr = Kb + k * RP + jj0;
            float4 ka = *(const float4*)kr;
            float4 kb = *(const float4*)(kr + 4);
            ull kd0 = dup2(ka.x), kd1 = dup2(ka.y), kd2 = dup2(ka.z), kd3 = dup2(ka.w);
            ull kd4 = dup2(kb.x), kd5 = dup2(kb.y), kd6 = dup2(kb.z), kd7 = dup2(kb.w);
            const float* qrp = Qb + k * RP + qq0;
            ull qp0 = *(const ull*)(qrp + 0);
            ull qp1 = *(const ull*)(qrp + 2);
            ull qp2 = *(const ull*)(qrp + 4);
            ull qp3 = *(const ull*)(qrp + 6);
            fma2(acc[0][0], qp0, kd0); fma2(acc[0][1], qp0, kd1);
            fma2(acc[0][2], qp0, kd2); fma2(acc[0][3], qp0, kd3);
            fma2(acc[0][4], qp0, kd4); fma2(acc[0][5], qp0, kd5);
            fma2(acc[0][6], qp0, kd6); fma2(acc[0][7], qp0, kd7);
            fma2(acc[1][0], qp1, kd0); fma2(acc[1][1], qp1, kd1);
            fma2(acc[1][2], qp1, kd2); fma2(acc[1][3], qp1, kd3);
            fma2(acc[1][4], qp1, kd4); fma2(acc[1][5], qp1, kd5);
            fma2(acc[1][6], qp1, kd6); fma2(acc[1][7], qp1, kd7);
            fma2(acc[2][0], qp2, kd0); fma2(acc[2][1], qp2, kd1);
            fma2(acc[2][2], qp2, kd2); fma2(acc[2][3], qp2, kd3);
            fma2(acc[2][4], qp2, kd4); fma2(acc[2][5], qp2, kd5);
            fma2(acc[2][6], qp2, kd6); fma2(acc[2][7], qp2, kd7);
            fma2(acc[3][0], qp3, kd0); fma2(acc[3][1], qp3, kd1);
            fma2(acc[3][2], qp3, kd2); fma2(acc[3][3], qp3, kd3);
            fma2(acc[3][4], qp3, kd4); fma2(acc[3][5], qp3, kd5);
            fma2(acc[3][6], qp3, kd6); fma2(acc[3][7], qp3, kd7);
        }
        __syncthreads();
    }

    // writeback scores (overwrites dbuf region; all compute done after last barrier)
    #pragma unroll
    for (int p = 0; p < 4; ++p)
        #pragma unroll
        for (int i = 0; i < 8; ++i) {
            float2 e = u2f(acc[p][i]);
            float2 o = make_float2(e.x * inv_scale, e.y * inv_scale);
            *(float2*)(cs + (jj0 + i) * RP + qq0 + 2 * p) = o;
        }
    __syncthreads();

    // ---- phase 3: fused nested softmax -> coefficient per key ----
    if (tid < QT) {
        const int q = tid;
        float m = -1e30f;
        for (int j = 0; j < nu; ++j) m = fmaxf(m, cs[j * RP + q]);
        float gs[NDEP];
        #pragma unroll
        for (int d = 0; d < NDEP; ++d) {
            float s = 0.f;
            for (int j = tab.bnd[d]; j < tab.bnd[d + 1]; ++j) {
                float e = __expf(cs[j * RP + q] - m);
                cs[j * RP + q] = e;
                s += e;
            }
            gs[d] = s;
        }
        float Z = 0.f, sa[NDEP];
        #pragma unroll
        for (int d = 0; d < NDEP; ++d) { Z += gs[d]; sa[d] = __fdividef(wv[d], Z); }
        float ss = 0.f;
        #pragma unroll
        for (int d = NDEP - 1; d >= 0; --d) { ss += sa[d]; sa[d] = ss; }
        #pragma unroll
        for (int d = 0; d < NDEP; ++d)
            for (int j = tab.bnd[d]; j < tab.bnd[d + 1]; ++j)
                cs[j * RP + q] *= sa[d];
    }

    // ---- phase 4: O[128q x 512d] = C . V ; 16 tiles (4 dc x 4 jt), double-buffered;
    //      key j=128 folded into a per-dc register epilogue ----
    const int fw    = tid >> 5;
    const int flane = tid & 31;
    const int dd0   = jj0;

    auto fillV = [&](int t, int s) {
        const int dc = t >> 2, jt = (t & 3) * 32;
        float* Vb = sm + VS_OFF + s * VS_STRIDE;
        #pragma unroll
        for (int rr = 0; rr < 4; ++rr) {
            int jr = fw + 8 * rr;
            float4 v = *(const float4*)(V + ((size_t)b * S_ + si[jt + jr]) * D_ + dc * 128 + flane * 4);
            *(float4*)(Vb + jr * RP + flane * 4) = v;
        }
    };

    ull av[4][8];
    const int si128 = si[128];

    fillV(0, 0);
    __syncthreads();

    #pragma unroll 1
    for (int t = 0; t < 16; ++t) {
        const int s  = t & 1;
        const int dc = t >> 2;
        if (t < 15) fillV(t + 1, s ^ 1);

        if ((t & 3) == 0) {
            #pragma unroll
            for (int p = 0; p < 4; ++p)
                #pragma unroll
                for (int i = 0; i < 8; ++i)
                    av[p][i] = 0ull;
        }

        const float* Vb = sm + VS_OFF + s * VS_STRIDE;
        const int jt = (t & 3) * 32;
        #pragma unroll 4
        for (int jj = 0; jj < 32; ++jj) {
            const float* vr = Vb + jj * RP + dd0;
            float4 va = *(const float4*)vr;
            float4 vb = *(const float4*)(vr + 4);
            ull vd0 = dup2(va.x), vd1 = dup2(va.y), vd2 = dup2(va.z), vd3 = dup2(va.w);
            ull vd4 = dup2(vb.x), vd5 = dup2(vb.y), vd6 = dup2(vb.z), vd7 = dup2(vb.w);
            const float* crp = cs + (jt + jj) * RP + qq0;
            ull cp0 = *(const ull*)(crp + 0);
            ull cp1 = *(const ull*)(crp + 2);
            ull cp2 = *(const ull*)(crp + 4);
            ull cp3 = *(const ull*)(crp + 6);
            fma2(av[0][0], cp0, vd0); fma2(av[0][1], cp0, vd1);
            fma2(av[0][2], cp0, vd2); fma2(av[0][3], cp0, vd3);
            fma2(av[0][4], cp0, vd4); fma2(av[0][5], cp0, vd5);
            fma2(av[0][6], cp0, vd6); fma2(av[0][7], cp0, vd7);
            fma2(av[1][0], cp1, vd0); fma2(av[1][1], cp1, vd1);
            fma2(av[1][2], cp1, vd2); fma2(av[1][3], cp1, vd3);
            fma2(av[1][4], cp1, vd4); fma2(av[1][5], cp1, vd5);
            fma2(av[1][6], cp1, vd6); fma2(av[1][7], cp1, vd7);
            fma2(av[2][0], cp2, vd0); fma2(av[2][1], cp2, vd1);
            fma2(av[2][2], cp2, vd2); fma2(av[2][3], cp2, vd3);
            fma2(av[2][4], cp2, vd4); fma2(av[2][5], cp2, vd5);
            fma2(av[2][6], cp2, vd6); fma2(av[2][7], cp2, vd7);
            fma2(av[3][0], cp3, vd0); fma2(av[3][1], cp3, vd1);
            fma2(av[3][2], cp3, vd2); fma2(av[3][3], cp3, vd3);
            fma2(av[3][4], cp3, vd4); fma2(av[3][5], cp3, vd5);
            fma2(av[3][6], cp3, vd6); fma2(av[3][7], cp3, vd7);
        }

        if ((t & 3) == 3) {
            // epilogue: key j=128 contribution for this dc chunk (L2-hit broadcast loads)
            const float* v128 = V + ((size_t)b * S_ + si128) * D_ + dc * 128 + dd0;
            float4 va = *(const float4*)v128;
            float4 vb = *(const float4*)(v128 + 4);
            ull vd0 = dup2(va.x), vd1 = dup2(va.y), vd2 = dup2(va.z), vd3 = dup2(va.w);
            ull vd4 = dup2(vb.x), vd5 = dup2(vb.y), vd6 = dup2(vb.z), vd7 = dup2(vb.w);
            const float* crp = cs + 128 * RP + qq0;
            ull cp0 = *(const ull*)(crp + 0);
            ull cp1 = *(const ull*)(crp + 2);
            ull cp2 = *(const ull*)(crp + 4);
            ull cp3 = *(const ull*)(crp + 6);
            fma2(av[0][0], cp0, vd0); fma2(av[0][1], cp0, vd1);
            fma2(av[0][2], cp0, vd2); fma2(av[0][3], cp0, vd3);
            fma2(av[0][4], cp0, vd4); fma2(av[0][5], cp0, vd5);
            fma2(av[0][6], cp0, vd6); fma2(av[0][7], cp0, vd7);
            fma2(av[1][0], cp1, vd0); fma2(av[1][1], cp1, vd1);
            fma2(av[1][2], cp1, vd2); fma2(av[1][3], cp1, vd3);
            fma2(av[1][4], cp1, vd4); fma2(av[1][5], cp1, vd5);
            fma2(av[1][6], cp1, vd6); fma2(av[1][7], cp1, vd7);
            fma2(av[2][0], cp2, vd0); fma2(av[2][1], cp2, vd1);
            fma2(av[2][2], cp2, vd2); fma2(av[2][3], cp2, vd3);
            fma2(av[2][4], cp2, vd4); fma2(av[2][5], cp2, vd5);
            fma2(av[2][6], cp2, vd6); fma2(av[2][7], cp2, vd7);
            fma2(av[3][0], cp3, vd0); fma2(av[3][1], cp3, vd1);
            fma2(av[3][2], cp3, vd2); fma2(av[3][3], cp3, vd3);
            fma2(av[3][4], cp3, vd4); fma2(av[3][5], cp3, vd5);
            fma2(av[3][6], cp3, vd6); fma2(av[3][7], cp3, vd7);

            // write O chunk
            #pragma unroll
            for (int p = 0; p < 4; ++p) {
                float2 e0 = u2f(av[p][0]), e1 = u2f(av[p][1]), e2 = u2f(av[p][2]), e3 = u2f(av[p][3]);
                float2 e4 = u2f(av[p][4]), e5 = u2f(av[p][5]), e6 = u2f(av[p][6]), e7 = u2f(av[p][7]);
                size_t base = ((size_t)b * S_ + q0blk + qq0 + 2 * p) * D_ + dc * 128 + dd0;
                *(float4*)(O + base + 0) = make_float4(e0.x, e1.x, e2.x, e3.x);
                *(float4*)(O + base + 4) = make_float4(e4.x, e5.x, e6.x, e7.x);
                *(float4*)(O + base + D_ + 0) = make_float4(e0.y, e1.y, e2.y, e3.y);
                *(float4*)(O + base + D_ + 4) = make_float4(e4.y, e5.y, e6.y, e7.y);
            }
        }
        __syncthreads();
    }
}

// ---------------- launch ----------------
extern "C" void kernel_launch(void* const* d_in, const int* in_sizes, int n_in,
                              void* d_out, int out_size)
{
    const float* Q  = (const float*)d_in[0];
    const float* K  = (const float*)d_in[1];
    const float* V  = (const float*)d_in[2];
    // d_in[3] = t (unused by the reference)
    const float* SW = (const float*)d_in[4];
    const float* ST = (const float*)d_in[5];
    float* O = (float*)d_out;

    const int smem_bytes = SMEM_FLOATS * (int)sizeof(float);  // 103488
    cudaFuncSetAttribute(ufa3_kernel, cudaFuncAttributeMaxDynamicSharedMemorySize, smem_bytes);

    dim3 grid(S_ / QT, B_);
    ufa3_kernel<<<grid, NTH, smem_bytes>>>(Q, K, V, SW, ST, O, g_tab);
}